// round 2
// baseline (speedup 1.0000x reference)
#include <cuda_runtime.h>
#include <math.h>

#define NSEG 256      // B*M
#define MLAB 32       // M
#define BSUB 8        // B
#define EPSN 1e-8f
#define DELTA_V 0.5f
#define TWO_DELTA_D 3.0f

// ---------------- device scratch (no allocations allowed) ----------------
__device__ float g_sums[NSEG * 16];
__device__ float g_cnts[NSEG];
__device__ float g_mus[NSEG * 16];
__device__ float g_invMc[NSEG];   // 1/(M * count)
__device__ float g_pull;
__device__ float g_push;

static const int P_BLOCKS  = 296;   // 2 CTAs/SM on 148 SMs
static const int P_THREADS = 512;

// ---------------- kernel 0: zero accumulators ----------------
__global__ void k_zero() {
    int t = threadIdx.x;
    for (int i = t; i < NSEG * 16; i += blockDim.x) g_sums[i] = 0.0f;
    if (t < NSEG) g_cnts[t] = 0.0f;
    if (t == 0) { g_pull = 0.0f; g_push = 0.0f; }
}

// ---------------- kernel 1: segment sums + counts of normalized x -------
__global__ __launch_bounds__(512, 2)
void k_pass1(const float4* __restrict__ out4,
             const int* __restrict__ lab,
             const int* __restrict__ sbi,
             int n) {
    __shared__ float s_sum[NSEG * 17];   // padded stride 17: conflict-free
    __shared__ float s_cnt[NSEG];
    int t = threadIdx.x;

    for (int i = t; i < NSEG * 17; i += blockDim.x) s_sum[i] = 0.0f;
    for (int i = t; i < NSEG; i += blockDim.x) s_cnt[i] = 0.0f;
    __syncthreads();

    // contiguous chunk per block, rounded to blockDim
    int per = (n + gridDim.x - 1) / gridDim.x;
    per = ((per + blockDim.x - 1) / blockDim.x) * blockDim.x;
    int start = blockIdx.x * per;
    int end   = start + per; if (end > n) end = n;

    float acc[16];
    float cnt = 0.0f;
    int cur = -1;
#pragma unroll
    for (int d = 0; d < 16; d++) acc[d] = 0.0f;

    for (int p = start + t; p < end; p += blockDim.x) {
        const float4* r = out4 + (size_t)p * 4;
        float4 a = r[0], b = r[1], c = r[2], e = r[3];
        float dot = a.x*a.x + a.y*a.y + a.z*a.z + a.w*a.w
                  + b.x*b.x + b.y*b.y + b.z*b.z + b.w*b.w
                  + c.x*c.x + c.y*c.y + c.z*c.z + c.w*c.w
                  + e.x*e.x + e.y*e.y + e.z*e.z + e.w*e.w;
        float invn = 1.0f / (sqrtf(dot) + EPSN);
        int seg = sbi[p] * MLAB + lab[p];

        if (seg != cur) {
            if (cur >= 0) {
#pragma unroll
                for (int d = 0; d < 16; d++) atomicAdd(&s_sum[cur * 17 + d], acc[d]);
                atomicAdd(&s_cnt[cur], cnt);
            }
            cur = seg; cnt = 0.0f;
#pragma unroll
            for (int d = 0; d < 16; d++) acc[d] = 0.0f;
        }
        acc[0]  += a.x * invn;  acc[1]  += a.y * invn;
        acc[2]  += a.z * invn;  acc[3]  += a.w * invn;
        acc[4]  += b.x * invn;  acc[5]  += b.y * invn;
        acc[6]  += b.z * invn;  acc[7]  += b.w * invn;
        acc[8]  += c.x * invn;  acc[9]  += c.y * invn;
        acc[10] += c.z * invn;  acc[11] += c.w * invn;
        acc[12] += e.x * invn;  acc[13] += e.y * invn;
        acc[14] += e.z * invn;  acc[15] += e.w * invn;
        cnt += 1.0f;
    }
    if (cur >= 0) {
#pragma unroll
        for (int d = 0; d < 16; d++) atomicAdd(&s_sum[cur * 17 + d], acc[d]);
        atomicAdd(&s_cnt[cur], cnt);
    }
    __syncthreads();

    // block flush: only segments actually touched (contiguous chunks hit ~32-64)
    for (int s = t; s < NSEG; s += blockDim.x) {
        float c0 = s_cnt[s];
        if (c0 != 0.0f) {
            atomicAdd(&g_cnts[s], c0);
#pragma unroll
            for (int d = 0; d < 16; d++)
                atomicAdd(&g_sums[s * 16 + d], s_sum[s * 17 + d]);
        }
    }
}

// ---------------- kernel 2: centroids + push term ----------------
__global__ void k_mid() {
    __shared__ float s_mu[NSEG * 17];
    __shared__ float s_red[NSEG];
    int s = threadIdx.x;             // 256 threads, one per segment
    float c  = g_cnts[s];
    float ic = 1.0f / c;
    float mi[16];
#pragma unroll
    for (int d = 0; d < 16; d++) {
        float m = g_sums[s * 16 + d] * ic;
        mi[d] = m;
        g_mus[s * 16 + d] = m;
        s_mu[s * 17 + d]  = m;
    }
    g_invMc[s] = 1.0f / ((float)MLAB * c);
    __syncthreads();

    int b = s >> 5, i = s & 31;
    float h = 0.0f;
    for (int j = 0; j < MLAB; j++) {
        if (j == i) continue;
        const float* mj = &s_mu[(b * 32 + j) * 17];
        float pd = 0.0f;
#pragma unroll
        for (int d = 0; d < 16; d++) pd += fabsf(mi[d] - mj[d]);
        float tt = TWO_DELTA_D - pd;
        if (tt > 0.0f) h += tt * tt;
    }
    s_red[s] = h;
    __syncthreads();
    for (int off = 128; off > 0; off >>= 1) {
        if (s < off) s_red[s] += s_red[s + off];
        __syncthreads();
    }
    if (s == 0) g_push = s_red[0] / ((float)MLAB * (float)(MLAB - 1));
}

// ---------------- kernel 3: pull term ----------------
__global__ __launch_bounds__(512, 2)
void k_pass2(const float4* __restrict__ out4,
             const int* __restrict__ lab,
             const int* __restrict__ sbi,
             int n) {
    __shared__ float s_mu[NSEG * 17];
    __shared__ float s_iv[NSEG];
    __shared__ float s_wred[16];
    int t = threadIdx.x;

    for (int i = t; i < NSEG * 16; i += blockDim.x) {
        int s = i >> 4, d = i & 15;
        s_mu[s * 17 + d] = g_mus[i];
    }
    for (int i = t; i < NSEG; i += blockDim.x) s_iv[i] = g_invMc[i];
    __syncthreads();

    int per = (n + gridDim.x - 1) / gridDim.x;
    per = ((per + blockDim.x - 1) / blockDim.x) * blockDim.x;
    int start = blockIdx.x * per;
    int end   = start + per; if (end > n) end = n;

    float local = 0.0f;
    for (int p = start + t; p < end; p += blockDim.x) {
        const float4* r = out4 + (size_t)p * 4;
        float4 a = r[0], b = r[1], c = r[2], e = r[3];
        float dot = a.x*a.x + a.y*a.y + a.z*a.z + a.w*a.w
                  + b.x*b.x + b.y*b.y + b.z*b.z + b.w*b.w
                  + c.x*c.x + c.y*c.y + c.z*c.z + c.w*c.w
                  + e.x*e.x + e.y*e.y + e.z*e.z + e.w*e.w;
        float invn = 1.0f / (sqrtf(dot) + EPSN);
        int seg = sbi[p] * MLAB + lab[p];
        const float* mu = &s_mu[seg * 17];
        float x[16];
        x[0]=a.x; x[1]=a.y; x[2]=a.z; x[3]=a.w;
        x[4]=b.x; x[5]=b.y; x[6]=b.z; x[7]=b.w;
        x[8]=c.x; x[9]=c.y; x[10]=c.z; x[11]=c.w;
        x[12]=e.x; x[13]=e.y; x[14]=e.z; x[15]=e.w;
        float dist = 0.0f;
#pragma unroll
        for (int d = 0; d < 16; d++) dist += fabsf(mu[d] - x[d] * invn);
        float tt = dist - DELTA_V;
        if (tt > 0.0f) local += tt * tt * s_iv[seg];
    }

    // block reduction: warp shuffle then cross-warp via shared
    for (int off = 16; off > 0; off >>= 1)
        local += __shfl_down_sync(0xFFFFFFFFu, local, off);
    int wid = t >> 5, lid = t & 31;
    if (lid == 0) s_wred[wid] = local;
    __syncthreads();
    if (wid == 0) {
        float v = (lid < (blockDim.x >> 5)) ? s_wred[lid] : 0.0f;
        for (int off = 16; off > 0; off >>= 1)
            v += __shfl_down_sync(0xFFFFFFFFu, v, off);
        if (lid == 0) atomicAdd(&g_pull, v);
    }
}

// ---------------- kernel 4: finalize ----------------
__global__ void k_final(float* out) {
    out[0] = (g_pull + g_push) * (1.0f / (float)BSUB);
}

extern "C" void kernel_launch(void* const* d_in, const int* in_sizes, int n_in,
                              void* d_out, int out_size) {
    const float4* out4 = (const float4*)d_in[0];
    const int*    lab  = (const int*)d_in[1];
    const int*    sbi  = (const int*)d_in[2];
    float* out = (float*)d_out;
    int n = in_sizes[1];   // N points (labels element count)

    k_zero<<<1, 512>>>();
    k_pass1<<<P_BLOCKS, P_THREADS>>>(out4, lab, sbi, n);
    k_mid<<<1, 256>>>();
    k_pass2<<<P_BLOCKS, P_THREADS>>>(out4, lab, sbi, n);
    k_final<<<1, 1>>>(out);
}

// round 3
// speedup vs baseline: 1.0677x; 1.0677x over previous
#include <cuda_runtime.h>
#include <math.h>

#define NSEG 256      // B*M
#define MLAB 32       // M
#define BSUB 8        // B
#define DELTA_V 0.5f
#define TWO_DELTA_D 3.0f

// ---------------- device scratch (self-cleaning across graph replays) ----
__device__ float g_sums[NSEG * 16] = {};
__device__ float g_cnts[NSEG]      = {};
__device__ float g_mus[NSEG * 16];
__device__ float g_invMc[NSEG];
__device__ float g_pull = 0.0f;
__device__ float g_push;

static const int P_BLOCKS  = 296;   // 2 CTAs/SM on 148 SMs
static const int P_THREADS = 512;

__device__ __forceinline__ void chunk_range(int n, int& start, int& end) {
    int per = (n + (int)gridDim.x - 1) / (int)gridDim.x;
    per = ((per + (int)blockDim.x - 1) / (int)blockDim.x) * (int)blockDim.x;
    start = blockIdx.x * per;
    end = start + per; if (end > n) end = n;
}

__device__ __forceinline__ float dot16(const float4& a, const float4& b,
                                       const float4& c, const float4& e) {
    return a.x*a.x + a.y*a.y + a.z*a.z + a.w*a.w
         + b.x*b.x + b.y*b.y + b.z*b.z + b.w*b.w
         + c.x*c.x + c.y*c.y + c.z*c.z + c.w*c.w
         + e.x*e.x + e.y*e.y + e.z*e.z + e.w*e.w;
}

// ---------------- kernel 1: segment sums + counts of normalized x -------
__global__ __launch_bounds__(512, 2)
void k_pass1(const float4* __restrict__ out4,
             const int* __restrict__ lab,
             const int* __restrict__ sbi,
             int n) {
    __shared__ float s_sum[NSEG * 17];   // padded stride 17: conflict-free
    __shared__ float s_cnt[NSEG];
    const int t  = threadIdx.x;
    const int bd = blockDim.x;

    for (int i = t; i < NSEG * 17; i += bd) s_sum[i] = 0.0f;
    for (int i = t; i < NSEG; i += bd)      s_cnt[i] = 0.0f;
    __syncthreads();

    int start, end;
    chunk_range(n, start, end);

    float acc[16];
    float cnt = 0.0f;
    int   cur = -1;
#pragma unroll
    for (int d = 0; d < 16; d++) acc[d] = 0.0f;

    auto flush = [&]() {
        if (cur >= 0) {
#pragma unroll
            for (int d = 0; d < 16; d++) atomicAdd(&s_sum[cur * 17 + d], acc[d]);
            atomicAdd(&s_cnt[cur], cnt);
        }
    };
    auto accpt = [&](int seg, const float4& a, const float4& b,
                     const float4& c, const float4& e, float inv) {
        if (seg != cur) {
            flush();
            cur = seg; cnt = 0.0f;
#pragma unroll
            for (int d = 0; d < 16; d++) acc[d] = 0.0f;
        }
        acc[0]  += a.x * inv;  acc[1]  += a.y * inv;
        acc[2]  += a.z * inv;  acc[3]  += a.w * inv;
        acc[4]  += b.x * inv;  acc[5]  += b.y * inv;
        acc[6]  += b.z * inv;  acc[7]  += b.w * inv;
        acc[8]  += c.x * inv;  acc[9]  += c.y * inv;
        acc[10] += c.z * inv;  acc[11] += c.w * inv;
        acc[12] += e.x * inv;  acc[13] += e.y * inv;
        acc[14] += e.z * inv;  acc[15] += e.w * inv;
        cnt += 1.0f;
    };

    const int base  = start + t;
    const int iters = (end - start) / bd;

    int i = 0;
    for (; i + 2 <= iters; i += 2) {          // 2-point batching for MLP
        int p0 = base + i * bd;
        int p1 = p0 + bd;
        const float4* r0 = out4 + (size_t)p0 * 4;
        const float4* r1 = out4 + (size_t)p1 * 4;
        float4 a0 = r0[0], b0 = r0[1], c0 = r0[2], e0 = r0[3];
        float4 a1 = r1[0], b1 = r1[1], c1 = r1[2], e1 = r1[3];
        int l0 = lab[p0], s0 = sbi[p0];
        int l1 = lab[p1], s1 = sbi[p1];
        float inv0 = rsqrtf(dot16(a0, b0, c0, e0));
        float inv1 = rsqrtf(dot16(a1, b1, c1, e1));
        accpt(s0 * MLAB + l0, a0, b0, c0, e0, inv0);
        accpt(s1 * MLAB + l1, a1, b1, c1, e1, inv1);
    }
    for (; i < iters; i++) {
        int p = base + i * bd;
        const float4* r = out4 + (size_t)p * 4;
        float4 a = r[0], b = r[1], c = r[2], e = r[3];
        float inv = rsqrtf(dot16(a, b, c, e));
        accpt(sbi[p] * MLAB + lab[p], a, b, c, e, inv);
    }
    {   // generic tail (not hit for these sizes, kept for safety)
        int p = start + iters * bd + t;
        if (p < end) {
            const float4* r = out4 + (size_t)p * 4;
            float4 a = r[0], b = r[1], c = r[2], e = r[3];
            float inv = rsqrtf(dot16(a, b, c, e));
            accpt(sbi[p] * MLAB + lab[p], a, b, c, e, inv);
        }
    }
    flush();
    __syncthreads();

    for (int s = t; s < NSEG; s += bd) {
        float c0 = s_cnt[s];
        if (c0 != 0.0f) {
            atomicAdd(&g_cnts[s], c0);
#pragma unroll
            for (int d = 0; d < 16; d++)
                atomicAdd(&g_sums[s * 16 + d], s_sum[s * 17 + d]);
        }
    }
}

// ---------------- kernel 2: centroids + push term + scratch reset -------
__global__ void k_mid() {
    __shared__ float s_mu[NSEG * 17];
    __shared__ float s_red[NSEG];
    int s = threadIdx.x;             // 256 threads, one per segment
    float c  = g_cnts[s];
    float ic = 1.0f / c;
    float mi[16];
#pragma unroll
    for (int d = 0; d < 16; d++) {
        float m = g_sums[s * 16 + d] * ic;
        mi[d] = m;
        g_mus[s * 16 + d] = m;
        s_mu[s * 17 + d]  = m;
        g_sums[s * 16 + d] = 0.0f;   // reset for next replay
    }
    g_invMc[s] = 1.0f / ((float)MLAB * c);
    g_cnts[s]  = 0.0f;               // reset for next replay
    __syncthreads();

    int b = s >> 5, i = s & 31;
    float h = 0.0f;
    for (int j = 0; j < MLAB; j++) {
        if (j == i) continue;
        const float* mj = &s_mu[(b * 32 + j) * 17];
        float pd = 0.0f;
#pragma unroll
        for (int d = 0; d < 16; d++) pd += fabsf(mi[d] - mj[d]);
        float tt = TWO_DELTA_D - pd;
        if (tt > 0.0f) h += tt * tt;
    }
    s_red[s] = h;
    __syncthreads();
    for (int off = 128; off > 0; off >>= 1) {
        if (s < off) s_red[s] += s_red[s + off];
        __syncthreads();
    }
    if (s == 0) g_push = s_red[0] / ((float)MLAB * (float)(MLAB - 1));
}

// ---------------- kernel 3: pull term (REVERSE order for L2 reuse) ------
__global__ __launch_bounds__(512, 2)
void k_pass2(const float4* __restrict__ out4,
             const int* __restrict__ lab,
             const int* __restrict__ sbi,
             int n) {
    __shared__ float s_mu[NSEG * 20];   // stride 20: float4-aligned, conflict-free
    __shared__ float s_iv[NSEG];
    __shared__ float s_wred[16];
    const int t  = threadIdx.x;
    const int bd = blockDim.x;

    for (int i = t; i < NSEG * 16; i += bd) {
        int s = i >> 4, d = i & 15;
        s_mu[s * 20 + d] = g_mus[i];
    }
    for (int i = t; i < NSEG; i += bd) s_iv[i] = g_invMc[i];
    __syncthreads();

    int start, end;
    chunk_range(n, start, end);

    float local = 0.0f;

    auto ppt = [&](int seg, const float4& a, const float4& b,
                   const float4& c, const float4& e, float inv) {
        const float4* m4 = (const float4*)&s_mu[seg * 20];
        float4 m0 = m4[0], m1 = m4[1], m2 = m4[2], m3 = m4[3];
        float dist =
              fabsf(fmaf(a.x, inv, -m0.x)) + fabsf(fmaf(a.y, inv, -m0.y))
            + fabsf(fmaf(a.z, inv, -m0.z)) + fabsf(fmaf(a.w, inv, -m0.w))
            + fabsf(fmaf(b.x, inv, -m1.x)) + fabsf(fmaf(b.y, inv, -m1.y))
            + fabsf(fmaf(b.z, inv, -m1.z)) + fabsf(fmaf(b.w, inv, -m1.w))
            + fabsf(fmaf(c.x, inv, -m2.x)) + fabsf(fmaf(c.y, inv, -m2.y))
            + fabsf(fmaf(c.z, inv, -m2.z)) + fabsf(fmaf(c.w, inv, -m2.w))
            + fabsf(fmaf(e.x, inv, -m3.x)) + fabsf(fmaf(e.y, inv, -m3.y))
            + fabsf(fmaf(e.z, inv, -m3.z)) + fabsf(fmaf(e.w, inv, -m3.w));
        float tt = dist - DELTA_V;
        if (tt > 0.0f) local += tt * tt * s_iv[seg];
    };

    const int base  = start + t;
    const int iters = (end - start) / bd;

    {   // generic tail first (not hit for these sizes)
        int p = start + iters * bd + t;
        if (p < end) {
            const float4* r = out4 + (size_t)p * 4;
            float4 a = r[0], b = r[1], c = r[2], e = r[3];
            float inv = rsqrtf(dot16(a, b, c, e));
            ppt(sbi[p] * MLAB + lab[p], a, b, c, e, inv);
        }
    }
    int i = iters;
    while (i >= 2) {                 // reverse walk, pair-batched
        i -= 2;
        int p0 = base + i * bd;
        int p1 = p0 + bd;
        const float4* r0 = out4 + (size_t)p0 * 4;
        const float4* r1 = out4 + (size_t)p1 * 4;
        float4 a1 = r1[0], b1 = r1[1], c1 = r1[2], e1 = r1[3];
        float4 a0 = r0[0], b0 = r0[1], c0 = r0[2], e0 = r0[3];
        int l1 = lab[p1], s1 = sbi[p1];
        int l0 = lab[p0], s0 = sbi[p0];
        float inv1 = rsqrtf(dot16(a1, b1, c1, e1));
        float inv0 = rsqrtf(dot16(a0, b0, c0, e0));
        ppt(s1 * MLAB + l1, a1, b1, c1, e1, inv1);
        ppt(s0 * MLAB + l0, a0, b0, c0, e0, inv0);
    }
    if (i == 1) {
        int p = base;
        const float4* r = out4 + (size_t)p * 4;
        float4 a = r[0], b = r[1], c = r[2], e = r[3];
        float inv = rsqrtf(dot16(a, b, c, e));
        ppt(sbi[p] * MLAB + lab[p], a, b, c, e, inv);
    }

    // block reduction: warp shuffle then cross-warp via shared
    for (int off = 16; off > 0; off >>= 1)
        local += __shfl_down_sync(0xFFFFFFFFu, local, off);
    int wid = t >> 5, lid = t & 31;
    if (lid == 0) s_wred[wid] = local;
    __syncthreads();
    if (wid == 0) {
        float v = (lid < (bd >> 5)) ? s_wred[lid] : 0.0f;
        for (int off = 16; off > 0; off >>= 1)
            v += __shfl_down_sync(0xFFFFFFFFu, v, off);
        if (lid == 0) atomicAdd(&g_pull, v);
    }
}

// ---------------- kernel 4: finalize + reset ----------------
__global__ void k_final(float* out) {
    out[0] = (g_pull + g_push) * (1.0f / (float)BSUB);
    g_pull = 0.0f;                   // reset for next replay
}

extern "C" void kernel_launch(void* const* d_in, const int* in_sizes, int n_in,
                              void* d_out, int out_size) {
    const float4* out4 = (const float4*)d_in[0];
    const int*    lab  = (const int*)d_in[1];
    const int*    sbi  = (const int*)d_in[2];
    float* out = (float*)d_out;
    int n = in_sizes[1];   // N points (labels element count)

    k_pass1<<<P_BLOCKS, P_THREADS>>>(out4, lab, sbi, n);
    k_mid<<<1, 256>>>();
    k_pass2<<<P_BLOCKS, P_THREADS>>>(out4, lab, sbi, n);
    k_final<<<1, 1>>>(out);
}

// round 4
// speedup vs baseline: 1.1315x; 1.0598x over previous
#include <cuda_runtime.h>
#include <math.h>

#define NSEG 256      // B*M
#define MLAB 32       // M
#define BSUB 8        // B
#define DELTA_V 0.5f
#define TWO_DELTA_D 3.0f

#define GRID 296      // 2 CTAs/SM * 148 SMs (GB300 has 152 -> all resident)
#define TPB  512

// ---------------- device scratch (self-cleaning across graph replays) ----
__device__ float    g_sums[NSEG * 16] = {};
__device__ float    g_cnts[NSEG]      = {};
__device__ float    g_pull = 0.0f;
__device__ float    g_push = 0.0f;
__device__ unsigned g_bar1 = 0u;
__device__ unsigned g_bar2 = 0u;

// shared layout (floats):
//   [0, 5120)      : pass2 s_mu (stride 20) / pass1 s_sum (stride 17, 4352 used)
//   [5120, 5376)   : s_cnt (pass1) / s_iv (pass2)
//   [5376, 5632)   : reduction scratch
#define SH_FLOATS (NSEG * 20 + NSEG + 256)

__device__ __forceinline__ float dot16(const float4& a, const float4& b,
                                       const float4& c, const float4& e) {
    return a.x*a.x + a.y*a.y + a.z*a.z + a.w*a.w
         + b.x*b.x + b.y*b.y + b.z*b.z + b.w*b.w
         + c.x*c.x + c.y*c.y + c.z*c.z + c.w*c.w
         + e.x*e.x + e.y*e.y + e.z*e.z + e.w*e.w;
}

__global__ __launch_bounds__(TPB, 2)
void k_fused(const float4* __restrict__ out4,
             const int* __restrict__ lab,
             const int* __restrict__ sbi,
             int n, float* __restrict__ out) {
    __shared__ float sh[SH_FLOATS];
    __shared__ int   sh_last;
    float* s_sum = sh;                 // stride 17 (pass1)
    float* s_mu  = sh;                 // stride 20 (pass2)
    float* s_cnt = sh + NSEG * 20;     // also s_iv in pass2
    float* s_red = sh + NSEG * 20 + NSEG;

    const int t  = threadIdx.x;
    const int bd = TPB;
    const int wid = t >> 5, lid = t & 31;

    // ---- chunk for this block ----
    int per = (n + GRID - 1) / GRID;
    per = ((per + bd - 1) / bd) * bd;
    int start = blockIdx.x * per;
    int end   = start + per; if (end > n) end = n;
    const int base  = start + t;
    const int iters = (end > start) ? (end - start) / bd : 0;

    // ================= PHASE A : segment sums of normalized x =============
    for (int i = t; i < NSEG * 17; i += bd) s_sum[i] = 0.0f;
    for (int i = t; i < NSEG; i += bd)      s_cnt[i] = 0.0f;
    __syncthreads();

    {
        float acc[16];
        float cnt = 0.0f;
        int   cur = -1;
#pragma unroll
        for (int d = 0; d < 16; d++) acc[d] = 0.0f;

        auto flush = [&]() {
            if (cur >= 0) {
#pragma unroll
                for (int d = 0; d < 16; d++) atomicAdd(&s_sum[cur * 17 + d], acc[d]);
                atomicAdd(&s_cnt[cur], cnt);
            }
        };
        auto accpt = [&](int seg, const float4& a, const float4& b,
                         const float4& c, const float4& e, float inv) {
            if (seg != cur) {
                flush();
                cur = seg; cnt = 0.0f;
#pragma unroll
                for (int d = 0; d < 16; d++) acc[d] = 0.0f;
            }
            acc[0]  += a.x * inv;  acc[1]  += a.y * inv;
            acc[2]  += a.z * inv;  acc[3]  += a.w * inv;
            acc[4]  += b.x * inv;  acc[5]  += b.y * inv;
            acc[6]  += b.z * inv;  acc[7]  += b.w * inv;
            acc[8]  += c.x * inv;  acc[9]  += c.y * inv;
            acc[10] += c.z * inv;  acc[11] += c.w * inv;
            acc[12] += e.x * inv;  acc[13] += e.y * inv;
            acc[14] += e.z * inv;  acc[15] += e.w * inv;
            cnt += 1.0f;
        };

        int i = 0;
        for (; i + 2 <= iters; i += 2) {      // 2-point batching for MLP
            int p0 = base + i * bd;
            int p1 = p0 + bd;
            const float4* r0 = out4 + (size_t)p0 * 4;
            const float4* r1 = out4 + (size_t)p1 * 4;
            float4 a0 = r0[0], b0 = r0[1], c0 = r0[2], e0 = r0[3];
            float4 a1 = r1[0], b1 = r1[1], c1 = r1[2], e1 = r1[3];
            int l0 = lab[p0], s0 = sbi[p0];
            int l1 = lab[p1], s1 = sbi[p1];
            float inv0 = rsqrtf(dot16(a0, b0, c0, e0));
            float inv1 = rsqrtf(dot16(a1, b1, c1, e1));
            accpt(s0 * MLAB + l0, a0, b0, c0, e0, inv0);
            accpt(s1 * MLAB + l1, a1, b1, c1, e1, inv1);
        }
        for (; i < iters; i++) {
            int p = base + i * bd;
            const float4* r = out4 + (size_t)p * 4;
            float4 a = r[0], b = r[1], c = r[2], e = r[3];
            float inv = rsqrtf(dot16(a, b, c, e));
            accpt(sbi[p] * MLAB + lab[p], a, b, c, e, inv);
        }
        {   // ragged tail (not hit at these sizes)
            int p = start + iters * bd + t;
            if (p < end) {
                const float4* r = out4 + (size_t)p * 4;
                float4 a = r[0], b = r[1], c = r[2], e = r[3];
                float inv = rsqrtf(dot16(a, b, c, e));
                accpt(sbi[p] * MLAB + lab[p], a, b, c, e, inv);
            }
        }
        flush();
    }
    __syncthreads();

    // block flush -> global atomics
    for (int s = t; s < NSEG; s += bd) {
        float c0 = s_cnt[s];
        if (c0 != 0.0f) {
            atomicAdd(&g_cnts[s], c0);
#pragma unroll
            for (int d = 0; d < 16; d++)
                atomicAdd(&g_sums[s * 16 + d], s_sum[s * 17 + d]);
        }
    }

    // ================= GRID BARRIER =================
    __threadfence();
    __syncthreads();
    if (t == 0) {
        atomicAdd(&g_bar1, 1u);
        while (*(volatile unsigned*)&g_bar1 < (unsigned)GRID) { }
    }
    __syncthreads();
    __threadfence();

    // ================= PHASE B : centroids (replicated per block) =========
    if (t < NSEG) {
        float c  = __ldcg(&g_cnts[t]);
        float ic = 1.0f / c;
        const float4* gs = (const float4*)&g_sums[t * 16];
        float4 m0 = __ldcg(gs + 0), m1 = __ldcg(gs + 1),
               m2 = __ldcg(gs + 2), m3 = __ldcg(gs + 3);
        float4* sm = (float4*)&s_mu[t * 20];
        m0.x *= ic; m0.y *= ic; m0.z *= ic; m0.w *= ic;
        m1.x *= ic; m1.y *= ic; m1.z *= ic; m1.w *= ic;
        m2.x *= ic; m2.y *= ic; m2.z *= ic; m2.w *= ic;
        m3.x *= ic; m3.y *= ic; m3.z *= ic; m3.w *= ic;
        sm[0] = m0; sm[1] = m1; sm[2] = m2; sm[3] = m3;
        s_cnt[t] = 1.0f / ((float)MLAB * c);    // s_iv
    }
    __syncthreads();

    // push term: block 0 only
    if (blockIdx.x == 0) {
        float h = 0.0f;
        if (t < NSEG) {
            int b = t >> 5, ii = t & 31;
            const float* mi = &s_mu[t * 20];
            for (int j = 0; j < MLAB; j++) {
                if (j == ii) continue;
                const float* mj = &s_mu[(b * 32 + j) * 20];
                float pd = 0.0f;
#pragma unroll
                for (int d = 0; d < 16; d++) pd += fabsf(mi[d] - mj[d]);
                float tt = TWO_DELTA_D - pd;
                if (tt > 0.0f) h += tt * tt;
            }
        }
        for (int off = 16; off > 0; off >>= 1)
            h += __shfl_down_sync(0xFFFFFFFFu, h, off);
        if (lid == 0) s_red[wid] = h;
        __syncthreads();
        if (t == 0) {
            float v = 0.0f;
            for (int w = 0; w < TPB / 32; w++) v += s_red[w];
            g_push = v / ((float)MLAB * (float)(MLAB - 1));
        }
        __syncthreads();   // keep s_red free before (unused) reuse; cheap
    }

    // ================= PHASE C : pull term (reverse walk, hot cache) ======
    float local = 0.0f;
    {
        auto ppt = [&](int seg, const float4& a, const float4& b,
                       const float4& c, const float4& e, float inv) {
            const float4* m4 = (const float4*)&s_mu[seg * 20];
            float4 m0 = m4[0], m1 = m4[1], m2 = m4[2], m3 = m4[3];
            float dist =
                  fabsf(fmaf(a.x, inv, -m0.x)) + fabsf(fmaf(a.y, inv, -m0.y))
                + fabsf(fmaf(a.z, inv, -m0.z)) + fabsf(fmaf(a.w, inv, -m0.w))
                + fabsf(fmaf(b.x, inv, -m1.x)) + fabsf(fmaf(b.y, inv, -m1.y))
                + fabsf(fmaf(b.z, inv, -m1.z)) + fabsf(fmaf(b.w, inv, -m1.w))
                + fabsf(fmaf(c.x, inv, -m2.x)) + fabsf(fmaf(c.y, inv, -m2.y))
                + fabsf(fmaf(c.z, inv, -m2.z)) + fabsf(fmaf(c.w, inv, -m2.w))
                + fabsf(fmaf(e.x, inv, -m3.x)) + fabsf(fmaf(e.y, inv, -m3.y))
                + fabsf(fmaf(e.z, inv, -m3.z)) + fabsf(fmaf(e.w, inv, -m3.w));
            float tt = dist - DELTA_V;
            if (tt > 0.0f) local += tt * tt * s_cnt[seg];   // s_iv
        };

        {   // ragged tail first
            int p = start + iters * bd + t;
            if (p < end) {
                const float4* r = out4 + (size_t)p * 4;
                float4 a = r[0], b = r[1], c = r[2], e = r[3];
                float inv = rsqrtf(dot16(a, b, c, e));
                ppt(sbi[p] * MLAB + lab[p], a, b, c, e, inv);
            }
        }
        int i = iters;
        while (i >= 2) {               // reverse: most-recently-streamed first
            i -= 2;
            int p0 = base + i * bd;
            int p1 = p0 + bd;
            const float4* r0 = out4 + (size_t)p0 * 4;
            const float4* r1 = out4 + (size_t)p1 * 4;
            float4 a1 = r1[0], b1 = r1[1], c1 = r1[2], e1 = r1[3];
            float4 a0 = r0[0], b0 = r0[1], c0 = r0[2], e0 = r0[3];
            int l1 = lab[p1], s1 = sbi[p1];
            int l0 = lab[p0], s0 = sbi[p0];
            float inv1 = rsqrtf(dot16(a1, b1, c1, e1));
            float inv0 = rsqrtf(dot16(a0, b0, c0, e0));
            ppt(s1 * MLAB + l1, a1, b1, c1, e1, inv1);
            ppt(s0 * MLAB + l0, a0, b0, c0, e0, inv0);
        }
        if (i == 1) {
            int p = base;
            const float4* r = out4 + (size_t)p * 4;
            float4 a = r[0], b = r[1], c = r[2], e = r[3];
            float inv = rsqrtf(dot16(a, b, c, e));
            ppt(sbi[p] * MLAB + lab[p], a, b, c, e, inv);
        }
    }

    // block reduction of pull
    for (int off = 16; off > 0; off >>= 1)
        local += __shfl_down_sync(0xFFFFFFFFu, local, off);
    if (lid == 0) s_red[wid] = local;
    __syncthreads();
    if (t == 0) {
        float v = 0.0f;
        for (int w = 0; w < TPB / 32; w++) v += s_red[w];
        atomicAdd(&g_pull, v);
    }

    // ================= EXIT: last block finalizes + resets ================
    if (t == 0) {
        __threadfence();
        unsigned old = atomicAdd(&g_bar2, 1u);
        sh_last = (old == (unsigned)GRID - 1u) ? 1 : 0;
    }
    __syncthreads();
    if (sh_last) {
        // all other blocks' fenced atomics are visible (we arrived last)
        for (int i = t; i < NSEG * 16; i += bd) g_sums[i] = 0.0f;
        for (int i = t; i < NSEG; i += bd)      g_cnts[i] = 0.0f;
        if (t == 0) {
            float pull = atomicAdd(&g_pull, 0.0f);
            float push = g_push;
            out[0] = (pull + push) * (1.0f / (float)BSUB);
            g_pull = 0.0f;
            g_push = 0.0f;
            g_bar1 = 0u;
            g_bar2 = 0u;
        }
    }
}

extern "C" void kernel_launch(void* const* d_in, const int* in_sizes, int n_in,
                              void* d_out, int out_size) {
    const float4* out4 = (const float4*)d_in[0];
    const int*    lab  = (const int*)d_in[1];
    const int*    sbi  = (const int*)d_in[2];
    float* out = (float*)d_out;
    int n = in_sizes[1];   // N points

    k_fused<<<GRID, TPB>>>(out4, lab, sbi, n, out);
}